// round 1
// baseline (speedup 1.0000x reference)
#include <cuda_runtime.h>
#include <cuda_fp16.h>

// Problem constants (fixed shapes)
#define BB    16
#define NN    65536
#define CC    256
#define RATIO 256
#define DINN  16
#define DOUTT 16

// Scratch (no allocation allowed -> __device__ globals)
__device__ __align__(16) __half g_s[DINN * BB * CC];     // s transposed: [i][b][k], fp16, 128 KB
__device__ __align__(16) float  g_wdt[CC * DOUTT * DINN]; // w_diag transposed: [c][o][i], 256 KB
__device__ __align__(16) float  g_off[BB * CC * DOUTT];   // off: [b][c][o], 256 KB

// ---------------------------------------------------------------------------
// Kernel T: transpose w_diag [o][i][c] -> [c][o*16+i]
// ---------------------------------------------------------------------------
__global__ __launch_bounds__(256) void kT(const float* __restrict__ wdiag) {
    int idx = blockIdx.x * 256 + threadIdx.x;   // 65536 total
    int c  = idx & 255;
    int oi = idx >> 8;
    g_wdt[c * 256 + oi] = wdiag[idx];           // read coalesced over c
}

// ---------------------------------------------------------------------------
// Kernel A: s[i][b][c] = sum_r x[b, permute_ids[c*256+r], i]  (stored fp16)
// grid (C, B), 128 threads. thread t: i = t&15, g = t>>4 (8 row-groups).
// Lanes 0..15 share a row with consecutive i -> 64B coalesced gather.
// ---------------------------------------------------------------------------
__global__ __launch_bounds__(128) void kA(const float* __restrict__ x,
                                          const int* __restrict__ pid) {
    int c = blockIdx.x, b = blockIdx.y;
    __shared__ int   ids[256];
    __shared__ float red[16][8];
    int t = threadIdx.x;
    ids[t]       = pid[c * 256 + t];
    ids[t + 128] = pid[c * 256 + t + 128];
    __syncthreads();

    int i = t & 15;
    int g = t >> 4;
    const float* xb = x + (size_t)b * NN * DINN;
    float acc = 0.f;
#pragma unroll 8
    for (int j = 0; j < 32; j++) {
        int r = g + 8 * j;
        acc += xb[(size_t)ids[r] * DINN + i];
    }
    red[i][g] = acc;
    __syncthreads();
    if (t < 16) {
        float v = 0.f;
#pragma unroll
        for (int gg = 0; gg < 8; gg++) v += red[t][gg];
        g_s[(t * BB + b) * CC + c] = __float2half(v);
    }
}

// ---------------------------------------------------------------------------
// Kernel B: off[b][c][o] = (1/N) * sum_{i,k} w_off[o][i][c][k] * s[b][k][i]
// grid C, 256 threads (8 warps). Warp w handles o = {2w, 2w+1}.
// Per i: stage fp16 slice sh[b][k] (8 KB); lanes span k (2 k's each via half2).
// HFMA2 accumulation, cross-lane butterfly reduce at the end.
// ---------------------------------------------------------------------------
__global__ __launch_bounds__(256) void kB(const float* __restrict__ woff) {
    int c    = blockIdx.x;
    int t    = threadIdx.x;
    int w    = t >> 5;
    int lane = t & 31;
    int o0 = 2 * w, o1 = o0 + 1;

    __shared__ __align__(16) __half2 sh[16 * 128];  // [b][h], h = k/2; 8 KB

    __half2 acc0[16], acc1[16];
#pragma unroll
    for (int b = 0; b < 16; b++) {
        acc0[b] = __float2half2_rn(0.f);
        acc1[b] = __float2half2_rn(0.f);
    }

    const uint4* gs4 = (const uint4*)g_s;  // 16 B = 8 halves

    for (int i = 0; i < 16; i++) {
        __syncthreads();
        // copy slice i: 8 KB = 512 uint4
        for (int q = t; q < 512; q += 256)
            ((uint4*)sh)[q] = gs4[i * 512 + q];
        __syncthreads();

        const float2* wb0 = (const float2*)(woff + (((size_t)o0 * 16 + i) * CC + c) * CC);
        const float2* wb1 = (const float2*)(woff + (((size_t)o1 * 16 + i) * CC + c) * CC);
#pragma unroll
        for (int stp = 0; stp < 4; stp++) {
            int h = stp * 32 + lane;            // half2 index, k = 2h
            float2 wf0 = wb0[h];
            float2 wf1 = wb1[h];
            __half2 wh0 = __floats2half2_rn(wf0.x, wf0.y);
            __half2 wh1 = __floats2half2_rn(wf1.x, wf1.y);
#pragma unroll
            for (int b = 0; b < 16; b++) {
                __half2 sv = sh[b * 128 + h];   // consecutive words across lanes
                acc0[b] = __hfma2(wh0, sv, acc0[b]);
                acc1[b] = __hfma2(wh1, sv, acc1[b]);
            }
        }
    }

    const float invN = 1.0f / (float)NN;
#pragma unroll
    for (int b = 0; b < 16; b++) {
        float f0 = __low2float(acc0[b]) + __high2float(acc0[b]);
        float f1 = __low2float(acc1[b]) + __high2float(acc1[b]);
#pragma unroll
        for (int off = 16; off > 0; off >>= 1) {
            f0 += __shfl_xor_sync(0xffffffffu, f0, off);
            f1 += __shfl_xor_sync(0xffffffffu, f1, off);
        }
        if (lane == 0) {
            g_off[((size_t)b * CC + c) * DOUTT + o0] = f0 * invN;
            g_off[((size_t)b * CC + c) * DOUTT + o1] = f1 * invN;
        }
    }
}

// ---------------------------------------------------------------------------
// Kernel C: out[b, permute_ids[c*256+r], o] =
//           sum_i wdt[c][o][i] * x[b, permute_ids[...], i] + off[b][c][o] + b1[o]
// grid (C, B), 256 threads (one p-row each). Weight tile + bias in smem.
// ---------------------------------------------------------------------------
__global__ __launch_bounds__(256) void kC(const float* __restrict__ x,
                                          const int* __restrict__ pid,
                                          const float* __restrict__ b1,
                                          float* __restrict__ out) {
    int c = blockIdx.x, b = blockIdx.y;
    __shared__ __align__(16) float wd[256];   // [o][i]
    __shared__ float bias[16];
    __shared__ int   ids[256];
    int t = threadIdx.x;
    wd[t]  = g_wdt[c * 256 + t];
    ids[t] = pid[c * 256 + t];
    if (t < 16) bias[t] = g_off[((size_t)b * CC + c) * DOUTT + t] + b1[t];
    __syncthreads();

    int n = ids[t];
    const float4* xr = (const float4*)(x + ((size_t)b * NN + n) * DINN);
    float4 x0 = xr[0], x1 = xr[1], x2 = xr[2], x3 = xr[3];

    float res[16];
#pragma unroll
    for (int o = 0; o < 16; o++) {
        const float4* wr = (const float4*)(wd + o * 16);
        float4 w0 = wr[0], w1 = wr[1], w2 = wr[2], w3 = wr[3];
        float a = bias[o];
        a += w0.x * x0.x + w0.y * x0.y + w0.z * x0.z + w0.w * x0.w;
        a += w1.x * x1.x + w1.y * x1.y + w1.z * x1.z + w1.w * x1.w;
        a += w2.x * x2.x + w2.y * x2.y + w2.z * x2.z + w2.w * x2.w;
        a += w3.x * x3.x + w3.y * x3.y + w3.z * x3.z + w3.w * x3.w;
        res[o] = a;
    }

    float4* outr = (float4*)(out + ((size_t)b * NN + n) * DINN);
    outr[0] = make_float4(res[0],  res[1],  res[2],  res[3]);
    outr[1] = make_float4(res[4],  res[5],  res[6],  res[7]);
    outr[2] = make_float4(res[8],  res[9],  res[10], res[11]);
    outr[3] = make_float4(res[12], res[13], res[14], res[15]);
}

// ---------------------------------------------------------------------------
// Launch. Input order per metadata: x, w_diag, w_off, b1, permute_ids.
// All on default stream -> sequential dependencies satisfied. Graph-safe.
// ---------------------------------------------------------------------------
extern "C" void kernel_launch(void* const* d_in, const int* in_sizes, int n_in,
                              void* d_out, int out_size) {
    const float* x     = (const float*)d_in[0];
    const float* wdiag = (const float*)d_in[1];
    const float* woff  = (const float*)d_in[2];
    const float* b1    = (const float*)d_in[3];
    const int*   pid   = (const int*)d_in[4];
    float* out = (float*)d_out;

    kT<<<256, 256>>>(wdiag);
    kA<<<dim3(CC, BB), 128>>>(x, pid);
    kB<<<CC, 256>>>(woff);
    kC<<<dim3(CC, BB), 256>>>(x, pid, b1, out);
}

// round 2
// speedup vs baseline: 1.1538x; 1.1538x over previous
#include <cuda_runtime.h>
#include <cuda_fp16.h>

#define BB    16
#define NN    65536
#define CC    256
#define RATIO 256
#define DINN  16
#define DOUTT 16

__device__ __align__(16) __half g_s[DINN * BB * CC];      // s: [i][b][c], fp16
__device__ __align__(16) float  g_wdt[CC * DOUTT * DINN]; // w_diag: [c][o][i]
__device__ __align__(16) float  g_off[BB * CC * DOUTT];   // off: [b][c][o]

__device__ __forceinline__ float4 shfl_xor_f4(float4 v, int m) {
    v.x = __shfl_xor_sync(0xffffffffu, v.x, m);
    v.y = __shfl_xor_sync(0xffffffffu, v.y, m);
    v.z = __shfl_xor_sync(0xffffffffu, v.z, m);
    v.w = __shfl_xor_sync(0xffffffffu, v.w, m);
    return v;
}
__device__ __forceinline__ float dot4(float4 a, float4 b) {
    return a.x*b.x + a.y*b.y + a.z*b.z + a.w*b.w;
}

// ---------------------------------------------------------------------------
// kT: transpose w_diag [o][i][c] -> [c][o*16+i]
// ---------------------------------------------------------------------------
__global__ __launch_bounds__(256) void kT(const float* __restrict__ wdiag) {
    int idx = blockIdx.x * 256 + threadIdx.x;
    int c  = idx & 255;
    int oi = idx >> 8;
    g_wdt[c * 256 + oi] = wdiag[idx];
}

// ---------------------------------------------------------------------------
// kA: s[i][b][c] = sum_r x[b, pid[c*256+r], i]   (fp16 out)
// 256 threads: q = t&3 (row quarter), g = t>>2 (64 row-groups, 4 rows each).
// One LDG.128 per warp covers 8 full rows -> 8 L1 wavefronts (vs 32 before).
// ---------------------------------------------------------------------------
__global__ __launch_bounds__(256) void kA(const float* __restrict__ x,
                                          const int* __restrict__ pid) {
    int c = blockIdx.x, b = blockIdx.y;
    __shared__ int ids[256];
    __shared__ float4 red[32];
    int t = threadIdx.x;
    int q = t & 3, g = t >> 2;
    int warp = t >> 5, lane = t & 31;
    ids[t] = pid[c * 256 + t];
    __syncthreads();

    const float* xb = x + (size_t)b * NN * DINN;
    float4 acc = make_float4(0.f, 0.f, 0.f, 0.f);
#pragma unroll
    for (int j = 0; j < 4; j++) {
        int n = ids[g + 64 * j];
        float4 v = ((const float4*)(xb + (size_t)n * DINN))[q];
        acc.x += v.x; acc.y += v.y; acc.z += v.z; acc.w += v.w;
    }
    // intra-warp reduce over the 8 row-groups (lane bits 2..4)
#pragma unroll
    for (int m = 4; m < 32; m <<= 1) {
        float4 o = shfl_xor_f4(acc, m);
        acc.x += o.x; acc.y += o.y; acc.z += o.z; acc.w += o.w;
    }
    if (lane < 4) red[warp * 4 + lane] = acc;
    __syncthreads();
    if (t < 32) {
        float4 v = red[t];  // t = w*4 + q
#pragma unroll
        for (int m = 4; m < 32; m <<= 1) {
            float4 o = shfl_xor_f4(v, m);
            v.x += o.x; v.y += o.y; v.z += o.z; v.w += o.w;
        }
        if (t < 4) {  // t == q holds s[4q..4q+3]
            int i0 = 4 * t;
            g_s[((i0 + 0) * BB + b) * CC + c] = __float2half(v.x);
            g_s[((i0 + 1) * BB + b) * CC + c] = __float2half(v.y);
            g_s[((i0 + 2) * BB + b) * CC + c] = __float2half(v.z);
            g_s[((i0 + 3) * BB + b) * CC + c] = __float2half(v.w);
        }
    }
}

// ---------------------------------------------------------------------------
// kB: off[b][c][o] = (1/N) * sum_{i,k} w_off[o][i][c][k] * s[b][k][i]
// (unchanged: w_off-read bound, HFMA2 accumulation)
// ---------------------------------------------------------------------------
__global__ __launch_bounds__(256) void kB(const float* __restrict__ woff) {
    int c    = blockIdx.x;
    int t    = threadIdx.x;
    int w    = t >> 5;
    int lane = t & 31;
    int o0 = 2 * w, o1 = o0 + 1;

    __shared__ __align__(16) __half2 sh[16 * 128];

    __half2 acc0[16], acc1[16];
#pragma unroll
    for (int b = 0; b < 16; b++) {
        acc0[b] = __float2half2_rn(0.f);
        acc1[b] = __float2half2_rn(0.f);
    }

    const uint4* gs4 = (const uint4*)g_s;

    for (int i = 0; i < 16; i++) {
        __syncthreads();
        for (int qq = t; qq < 512; qq += 256)
            ((uint4*)sh)[qq] = gs4[i * 512 + qq];
        __syncthreads();

        const float2* wb0 = (const float2*)(woff + (((size_t)o0 * 16 + i) * CC + c) * CC);
        const float2* wb1 = (const float2*)(woff + (((size_t)o1 * 16 + i) * CC + c) * CC);
#pragma unroll
        for (int stp = 0; stp < 4; stp++) {
            int h = stp * 32 + lane;
            float2 wf0 = wb0[h];
            float2 wf1 = wb1[h];
            __half2 wh0 = __floats2half2_rn(wf0.x, wf0.y);
            __half2 wh1 = __floats2half2_rn(wf1.x, wf1.y);
#pragma unroll
            for (int b = 0; b < 16; b++) {
                __half2 sv = sh[b * 128 + h];
                acc0[b] = __hfma2(wh0, sv, acc0[b]);
                acc1[b] = __hfma2(wh1, sv, acc1[b]);
            }
        }
    }

    const float invN = 1.0f / (float)NN;
#pragma unroll
    for (int b = 0; b < 16; b++) {
        float f0 = __low2float(acc0[b]) + __high2float(acc0[b]);
        float f1 = __low2float(acc1[b]) + __high2float(acc1[b]);
#pragma unroll
        for (int off = 16; off > 0; off >>= 1) {
            f0 += __shfl_xor_sync(0xffffffffu, f0, off);
            f1 += __shfl_xor_sync(0xffffffffu, f1, off);
        }
        if (lane == 0) {
            g_off[((size_t)b * CC + c) * DOUTT + o0] = f0 * invN;
            g_off[((size_t)b * CC + c) * DOUTT + o1] = f1 * invN;
        }
    }
}

// ---------------------------------------------------------------------------
// kC: out[b, n, 4q+oo] = sum_i w[4q+oo][i]*x[b,n,i] + off[b][c][.] + b1
// 4 lanes per row -> 8 wavefronts per LDG.128/STG.128.
// Other quarters via 3x shfl_xor; weights held in 64 regs in q^p i-order.
// ---------------------------------------------------------------------------
__global__ __launch_bounds__(256) void kC(const float* __restrict__ x,
                                          const int* __restrict__ pid,
                                          const float* __restrict__ b1,
                                          float* __restrict__ out) {
    int c = blockIdx.x, b = blockIdx.y;
    __shared__ __align__(16) float wd[256];
    __shared__ float bsh[16];
    __shared__ int ids[256];
    int t = threadIdx.x;
    int q = t & 3, g = t >> 2;

    wd[t]  = g_wdt[c * 256 + t];
    ids[t] = pid[c * 256 + t];
    if (t < 16) bsh[t] = g_off[((size_t)b * CC + c) * DOUTT + t] + b1[t];
    __syncthreads();

    // weights for o = 4q+oo, i-blocks permuted to shuffle arrival order q^p
    float4 wreg[4][4];
    float  bs[4];
#pragma unroll
    for (int oo = 0; oo < 4; oo++) {
        int o = 4 * q + oo;
        bs[oo] = bsh[o];
#pragma unroll
        for (int p = 0; p < 4; p++) {
            int qq = q ^ p;
            wreg[oo][p] = *(const float4*)(wd + o * 16 + 4 * qq);
        }
    }

    const float* xb = x + (size_t)b * NN * DINN;
    float* ob = out + (size_t)b * NN * DOUTT;

#pragma unroll
    for (int j = 0; j < 4; j++) {
        int n = ids[g + 64 * j];
        float4 X0 = ((const float4*)(xb + (size_t)n * DINN))[q];
        float4 X1 = shfl_xor_f4(X0, 1);
        float4 X2 = shfl_xor_f4(X0, 2);
        float4 X3 = shfl_xor_f4(X0, 3);

        float r0 = bs[0], r1 = bs[1], r2 = bs[2], r3 = bs[3];
        r0 += dot4(wreg[0][0], X0) + dot4(wreg[0][1], X1) + dot4(wreg[0][2], X2) + dot4(wreg[0][3], X3);
        r1 += dot4(wreg[1][0], X0) + dot4(wreg[1][1], X1) + dot4(wreg[1][2], X2) + dot4(wreg[1][3], X3);
        r2 += dot4(wreg[2][0], X0) + dot4(wreg[2][1], X1) + dot4(wreg[2][2], X2) + dot4(wreg[2][3], X3);
        r3 += dot4(wreg[3][0], X0) + dot4(wreg[3][1], X1) + dot4(wreg[3][2], X2) + dot4(wreg[3][3], X3);

        ((float4*)(ob + (size_t)n * DOUTT))[q] = make_float4(r0, r1, r2, r3);
    }
}

extern "C" void kernel_launch(void* const* d_in, const int* in_sizes, int n_in,
                              void* d_out, int out_size) {
    const float* x     = (const float*)d_in[0];
    const float* wdiag = (const float*)d_in[1];
    const float* woff  = (const float*)d_in[2];
    const float* b1    = (const float*)d_in[3];
    const int*   pid   = (const int*)d_in[4];
    float* out = (float*)d_out;

    kT<<<256, 256>>>(wdiag);
    kA<<<dim3(CC, BB), 256>>>(x, pid);
    kB<<<CC, 256>>>(woff);
    kC<<<dim3(CC, BB), 256>>>(x, pid, b1, out);
}